// round 3
// baseline (speedup 1.0000x reference)
#include <cuda_runtime.h>
#include <cuda_bf16.h>
#include <cfloat>

#define LEVELS 255.0f
#define EPS 1e-8f
#define NUM_ROWS 4096
#define GRID 296   // 148 SMs x 2 resident CTAs: persistent, zero wave transitions

// Persistent-CTA per-channel fake quant.
// Row = 16384 fp32 = 4096 float4; 1024 threads x 4 float4 = row in registers.
// Each CTA grid-strides over rows; stores of row i overlap loads of row i+1.

__global__ __launch_bounds__(1024, 2)
void perchannel_quant_kernel(const float* __restrict__ x,
                             float* __restrict__ out)
{
    const int tid  = threadIdx.x;
    const int lane = tid & 31;
    const int wid  = tid >> 5;

    __shared__ float smn[32];
    __shared__ float smx[32];

    for (int row = blockIdx.x; row < NUM_ROWS; row += GRID) {
        const float4* __restrict__ xrow =
            reinterpret_cast<const float4*>(x) + (size_t)row * 4096;
        float4* __restrict__ orow =
            reinterpret_cast<float4*>(out) + (size_t)row * 4096;

        // ---- load 4 float4 per thread, coalesced, evict-first ----
        float4 v0 = __ldcs(&xrow[tid]);
        float4 v1 = __ldcs(&xrow[tid + 1024]);
        float4 v2 = __ldcs(&xrow[tid + 2048]);
        float4 v3 = __ldcs(&xrow[tid + 3072]);

        // ---- per-thread min/max ----
        float mn = fminf(fminf(fminf(v0.x, v0.y), fminf(v0.z, v0.w)),
                         fminf(fminf(v1.x, v1.y), fminf(v1.z, v1.w)));
        float mx = fmaxf(fmaxf(fmaxf(v0.x, v0.y), fmaxf(v0.z, v0.w)),
                         fmaxf(fmaxf(v1.x, v1.y), fmaxf(v1.z, v1.w)));
        mn = fminf(mn, fminf(fminf(fminf(v2.x, v2.y), fminf(v2.z, v2.w)),
                             fminf(fminf(v3.x, v3.y), fminf(v3.z, v3.w))));
        mx = fmaxf(mx, fmaxf(fmaxf(fmaxf(v2.x, v2.y), fmaxf(v2.z, v2.w)),
                             fmaxf(fmaxf(v3.x, v3.y), fmaxf(v3.z, v3.w))));

        // ---- warp reduce ----
        #pragma unroll
        for (int off = 16; off > 0; off >>= 1) {
            mn = fminf(mn, __shfl_xor_sync(0xffffffffu, mn, off));
            mx = fmaxf(mx, __shfl_xor_sync(0xffffffffu, mx, off));
        }

        // ---- block reduce: ONE barrier, every warp redundantly reduces ----
        if (lane == 0) { smn[wid] = mn; smx[wid] = mx; }
        __syncthreads();

        mn = smn[lane];
        mx = smx[lane];
        #pragma unroll
        for (int off = 16; off > 0; off >>= 1) {
            mn = fminf(mn, __shfl_xor_sync(0xffffffffu, mn, off));
            mx = fmaxf(mx, __shfl_xor_sync(0xffffffffu, mx, off));
        }

        const float x_min = fminf(mn, 0.0f);
        const float x_max = fmaxf(mx, 0.0f);
        const float scale = fmaxf((x_max - x_min) * (1.0f / LEVELS), EPS);
        const float zero  = rintf(-x_min / scale);
        const float inv_scale = 1.0f / scale;

        // smn/smx are re-written next iteration only after the next
        // __syncthreads-protected load phase; but warps may race ahead to
        // the `if (lane==0) smn[wid]=...` of the NEXT row before slow warps
        // read this row's partials. Need a barrier separating read from
        // next write:
        __syncthreads();

        // ---- quantize from registers, store evict-first ----
        #define QUANT(e) do { \
            float q = rintf((e) * inv_scale) + zero; \
            q = fminf(fmaxf(q, 0.0f), LEVELS); \
            (e) = (q - zero) * scale; \
        } while (0)

        QUANT(v0.x); QUANT(v0.y); QUANT(v0.z); QUANT(v0.w);
        QUANT(v1.x); QUANT(v1.y); QUANT(v1.z); QUANT(v1.w);
        QUANT(v2.x); QUANT(v2.y); QUANT(v2.z); QUANT(v2.w);
        QUANT(v3.x); QUANT(v3.y); QUANT(v3.z); QUANT(v3.w);
        #undef QUANT

        __stcs(&orow[tid],        v0);
        __stcs(&orow[tid + 1024], v1);
        __stcs(&orow[tid + 2048], v2);
        __stcs(&orow[tid + 3072], v3);
    }
}

extern "C" void kernel_launch(void* const* d_in, const int* in_sizes, int n_in,
                              void* d_out, int out_size)
{
    const float* x = (const float*)d_in[0];
    float* out = (float*)d_out;
    perchannel_quant_kernel<<<GRID, 1024>>>(x, out);
}

// round 5
// speedup vs baseline: 1.1935x; 1.1935x over previous
#include <cuda_runtime.h>
#include <cuda_bf16.h>
#include <cfloat>

#define LEVELS 255.0f
#define EPS 1e-8f

// One CTA per row (channel). Row = 16384 fp32 = 4096 float4.
// 1024 threads * 4 float4 each = full row held in registers.
// Single pass over HBM: load -> block min/max reduce -> quantize -> store.
// v4 (resubmit after infra failure): R2 structure + shortened epilogue:
//   clip(rint(x/s)+z,0,255)-z == clip(rint(x/s), -z, 255-z)  (exact, z integer)

__global__ __launch_bounds__(1024, 2)
void perchannel_quant_kernel(const float* __restrict__ x,
                             float* __restrict__ out)
{
    const int row = blockIdx.x;
    const int tid = threadIdx.x;

    const float4* __restrict__ xrow =
        reinterpret_cast<const float4*>(x) + (size_t)row * 4096;
    float4* __restrict__ orow =
        reinterpret_cast<float4*>(out) + (size_t)row * 4096;

    // ---- load 4 float4 per thread, coalesced, evict-first ----
    float4 v0 = __ldcs(&xrow[tid]);
    float4 v1 = __ldcs(&xrow[tid + 1024]);
    float4 v2 = __ldcs(&xrow[tid + 2048]);
    float4 v3 = __ldcs(&xrow[tid + 3072]);

    // ---- per-thread min/max ----
    float mn = fminf(fminf(fminf(v0.x, v0.y), fminf(v0.z, v0.w)),
                     fminf(fminf(v1.x, v1.y), fminf(v1.z, v1.w)));
    float mx = fmaxf(fmaxf(fmaxf(v0.x, v0.y), fmaxf(v0.z, v0.w)),
                     fmaxf(fmaxf(v1.x, v1.y), fmaxf(v1.z, v1.w)));
    mn = fminf(mn, fminf(fminf(fminf(v2.x, v2.y), fminf(v2.z, v2.w)),
                         fminf(fminf(v3.x, v3.y), fminf(v3.z, v3.w))));
    mx = fmaxf(mx, fmaxf(fmaxf(fmaxf(v2.x, v2.y), fmaxf(v2.z, v2.w)),
                         fmaxf(fmaxf(v3.x, v3.y), fmaxf(v3.z, v3.w))));

    // ---- warp reduce ----
    #pragma unroll
    for (int off = 16; off > 0; off >>= 1) {
        mn = fminf(mn, __shfl_xor_sync(0xffffffffu, mn, off));
        mx = fmaxf(mx, __shfl_xor_sync(0xffffffffu, mx, off));
    }

    // ---- block reduce: partials to smem, ONE barrier, then every warp
    //      redundantly butterfly-reduces all 32 partials. ----
    __shared__ float smn[32];
    __shared__ float smx[32];

    const int lane = tid & 31;
    const int wid  = tid >> 5;
    if (lane == 0) { smn[wid] = mn; smx[wid] = mx; }
    __syncthreads();

    mn = smn[lane];
    mx = smx[lane];
    #pragma unroll
    for (int off = 16; off > 0; off >>= 1) {
        mn = fminf(mn, __shfl_xor_sync(0xffffffffu, mn, off));
        mx = fmaxf(mx, __shfl_xor_sync(0xffffffffu, mx, off));
    }

    const float x_min = fminf(mn, 0.0f);
    const float x_max = fmaxf(mx, 0.0f);
    const float scale = fmaxf((x_max - x_min) * (1.0f / LEVELS), EPS);
    const float zero  = rintf(-x_min / scale);
    const float inv_scale = 1.0f / scale;
    const float qlo = -zero;           // clamp bounds in centered q-domain
    const float qhi = LEVELS - zero;

    // ---- quantize from registers, store evict-first ----
    #define QUANT(e) do { \
        float q = rintf((e) * inv_scale); \
        q = fminf(fmaxf(q, qlo), qhi); \
        (e) = q * scale; \
    } while (0)

    QUANT(v0.x); QUANT(v0.y); QUANT(v0.z); QUANT(v0.w);
    QUANT(v1.x); QUANT(v1.y); QUANT(v1.z); QUANT(v1.w);
    QUANT(v2.x); QUANT(v2.y); QUANT(v2.z); QUANT(v2.w);
    QUANT(v3.x); QUANT(v3.y); QUANT(v3.z); QUANT(v3.w);
    #undef QUANT

    __stcs(&orow[tid],        v0);
    __stcs(&orow[tid + 1024], v1);
    __stcs(&orow[tid + 2048], v2);
    __stcs(&orow[tid + 3072], v3);
}

extern "C" void kernel_launch(void* const* d_in, const int* in_sizes, int n_in,
                              void* d_out, int out_size)
{
    const float* x = (const float*)d_in[0];
    float* out = (float*)d_out;
    perchannel_quant_kernel<<<4096, 1024>>>(x, out);
}

// round 6
// speedup vs baseline: 1.1940x; 1.0004x over previous
#include <cuda_runtime.h>
#include <cuda_bf16.h>
#include <cfloat>

#define LEVELS 255.0f
#define EPS 1e-8f

// One CTA per row. Row = 16384 fp32 = 4096 float4; 1024 threads.
// v6: anti-spill variant. Only v0/v1 (8 floats) stay live in registers
// across the block reduction; v2/v3 are staged in shared memory (32KB/CTA).
// Hypothesis: regs==32 (the exact cap) in v2..v5 meant ptxas spilled part
// of the row to local memory; smem staging removes that.

__global__ __launch_bounds__(1024, 2)
void perchannel_quant_kernel(const float* __restrict__ x,
                             float* __restrict__ out)
{
    const int row = blockIdx.x;
    const int tid = threadIdx.x;

    const float4* __restrict__ xrow =
        reinterpret_cast<const float4*>(x) + (size_t)row * 4096;
    float4* __restrict__ orow =
        reinterpret_cast<float4*>(out) + (size_t)row * 4096;

    __shared__ float4 sv2[1024];
    __shared__ float4 sv3[1024];
    __shared__ float smn[32];
    __shared__ float smx[32];

    // ---- load 4 float4 per thread, coalesced, evict-first ----
    float4 v0 = __ldcs(&xrow[tid]);
    float4 v1 = __ldcs(&xrow[tid + 1024]);
    float4 v2 = __ldcs(&xrow[tid + 2048]);
    float4 v3 = __ldcs(&xrow[tid + 3072]);

    // stage v2/v3 to smem so their registers die before the barrier
    sv2[tid] = v2;
    sv3[tid] = v3;

    // ---- per-thread min/max over all 16 values ----
    float mn = fminf(fminf(fminf(v0.x, v0.y), fminf(v0.z, v0.w)),
                     fminf(fminf(v1.x, v1.y), fminf(v1.z, v1.w)));
    float mx = fmaxf(fmaxf(fmaxf(v0.x, v0.y), fmaxf(v0.z, v0.w)),
                     fmaxf(fmaxf(v1.x, v1.y), fmaxf(v1.z, v1.w)));
    mn = fminf(mn, fminf(fminf(fminf(v2.x, v2.y), fminf(v2.z, v2.w)),
                         fminf(fminf(v3.x, v3.y), fminf(v3.z, v3.w))));
    mx = fmaxf(mx, fmaxf(fmaxf(fmaxf(v2.x, v2.y), fmaxf(v2.z, v2.w)),
                         fmaxf(fmaxf(v3.x, v3.y), fmaxf(v3.z, v3.w))));

    // ---- warp reduce ----
    #pragma unroll
    for (int off = 16; off > 0; off >>= 1) {
        mn = fminf(mn, __shfl_xor_sync(0xffffffffu, mn, off));
        mx = fmaxf(mx, __shfl_xor_sync(0xffffffffu, mx, off));
    }

    // ---- block reduce: ONE barrier, every warp redundantly reduces ----
    const int lane = tid & 31;
    const int wid  = tid >> 5;
    if (lane == 0) { smn[wid] = mn; smx[wid] = mx; }
    __syncthreads();   // also orders sv2/sv3 stores before re-read

    mn = smn[lane];
    mx = smx[lane];
    #pragma unroll
    for (int off = 16; off > 0; off >>= 1) {
        mn = fminf(mn, __shfl_xor_sync(0xffffffffu, mn, off));
        mx = fmaxf(mx, __shfl_xor_sync(0xffffffffu, mx, off));
    }

    const float x_min = fminf(mn, 0.0f);
    const float x_max = fmaxf(mx, 0.0f);
    const float scale = fmaxf((x_max - x_min) * (1.0f / LEVELS), EPS);
    const float zero  = rintf(-x_min / scale);
    const float inv_scale = 1.0f / scale;
    const float qlo = -zero;           // clamp bounds in centered q-domain
    const float qhi = LEVELS - zero;

    #define QUANT(e) do { \
        float q = rintf((e) * inv_scale); \
        q = fminf(fmaxf(q, qlo), qhi); \
        (e) = q * scale; \
    } while (0)

    // ---- quantize reg-resident halves, store ----
    QUANT(v0.x); QUANT(v0.y); QUANT(v0.z); QUANT(v0.w);
    QUANT(v1.x); QUANT(v1.y); QUANT(v1.z); QUANT(v1.w);
    __stcs(&orow[tid],        v0);
    __stcs(&orow[tid + 1024], v1);

    // ---- re-read staged halves from smem, quantize, store ----
    float4 w2 = sv2[tid];
    float4 w3 = sv3[tid];
    QUANT(w2.x); QUANT(w2.y); QUANT(w2.z); QUANT(w2.w);
    QUANT(w3.x); QUANT(w3.y); QUANT(w3.z); QUANT(w3.w);
    __stcs(&orow[tid + 2048], w2);
    __stcs(&orow[tid + 3072], w3);
    #undef QUANT
}

extern "C" void kernel_launch(void* const* d_in, const int* in_sizes, int n_in,
                              void* d_out, int out_size)
{
    const float* x = (const float*)d_in[0];
    float* out = (float*)d_out;
    perchannel_quant_kernel<<<4096, 1024>>>(x, out);
}